// round 9
// baseline (speedup 1.0000x reference)
#include <cuda_runtime.h>
#include <cuda_bf16.h>
#include <cstdint>

// ---------------- problem constants ----------------
#define BATCH 16
#define SEQ   100
#define DIM   8192
#define PDIM  100
#define TPAD  102
#define M_ROWS 1632
#define N_COLS 300
#define NPAD   320
#define KSPLITS 8
#define K_PER  (DIM / KSPLITS)    // 1024
#define KC     32                 // k per chunk
#define NCHUNK (K_PER / KC)       // 32

// GEMM tiling
#define BM 64
#define BN 160
#define NTHREADS 256
#define NSTAGES 2

// ---------------- global scratch ----------------
__device__ float g_Y[KSPLITS][M_ROWS * N_COLS];            // 15.7 MB
// weights: bf16 hi/lo split, natural layout [k][NPAD]
__device__ __nv_bfloat16 g_Bh[(size_t)DIM * NPAD];
__device__ __nv_bfloat16 g_Bl[(size_t)DIM * NPAD];

// ---------------- smem layout ----------------
#define PITCH_A 80                    // 32 bf16 + 8 pad
#define PITCH_BK 336                  // 160 bf16 + 8 pad (odd 16B stride -> conflict-free)
#define ST_AH 0
#define ST_AL (BM * PITCH_A)                         // 5120
#define ST_BH (2 * BM * PITCH_A)                     // 10240
#define ST_BL (2 * BM * PITCH_A + KC * PITCH_BK)     // 20992
#define STAGE_BYTES (2 * BM * PITCH_A + 2 * KC * PITCH_BK)   // 31744
#define SMEM_TOTAL (NSTAGES * STAGE_BYTES)           // 63488 -> 3 CTAs/SM

// ---------------- helpers ----------------
__device__ __forceinline__ uint32_t smem_u32(const void* p) {
    uint32_t a;
    asm("{ .reg .u64 t; cvta.to.shared.u64 t, %1; cvt.u32.u64 %0, t; }" : "=r"(a) : "l"(p));
    return a;
}
__device__ __forceinline__ void ldmx4(uint32_t (&r)[4], uint32_t addr) {
    asm volatile("ldmatrix.sync.aligned.m8n8.x4.shared.b16 {%0,%1,%2,%3}, [%4];"
                 : "=r"(r[0]), "=r"(r[1]), "=r"(r[2]), "=r"(r[3]) : "r"(addr));
}
__device__ __forceinline__ void ldmx2t(uint32_t (&r)[2], uint32_t addr) {
    asm volatile("ldmatrix.sync.aligned.m8n8.x2.trans.shared.b16 {%0,%1}, [%2];"
                 : "=r"(r[0]), "=r"(r[1]) : "r"(addr));
}
__device__ __forceinline__ void mma_bf16(float (&d)[4], const uint32_t (&a)[4],
                                         const uint32_t (&b)[2]) {
    asm volatile("mma.sync.aligned.m16n8k16.row.col.f32.bf16.bf16.f32 "
                 "{%0,%1,%2,%3},{%4,%5,%6,%7},{%8,%9},{%0,%1,%2,%3};"
                 : "+f"(d[0]), "+f"(d[1]), "+f"(d[2]), "+f"(d[3])
                 : "r"(a[0]), "r"(a[1]), "r"(a[2]), "r"(a[3]), "r"(b[0]), "r"(b[1]));
}
#define CP16(dst, src) \
    asm volatile("cp.async.cg.shared.global [%0], [%1], 16;" :: "r"(dst), "l"(src))
#define CP_COMMIT() asm volatile("cp.async.commit_group;" ::: "memory")
#define CP_WAIT1()  asm volatile("cp.async.wait_group 1;" ::: "memory")
#define CP_WAIT0()  asm volatile("cp.async.wait_group 0;" ::: "memory")

// ---------------------------------------------------------------------------
// Pre-pass: bf16 hi/lo split, no transpose, no div/mod. One block per k-row.
// ---------------------------------------------------------------------------
__global__ __launch_bounds__(160)
void conv_w(const float* __restrict__ wq, const float* __restrict__ wk,
            const float* __restrict__ wv)
{
    const int k = blockIdx.x;
    const size_t kb = (size_t)k * NPAD;
    const size_t wb = (size_t)k * PDIM;
#pragma unroll
    for (int j = 0; j < 2; j++) {
        int n = threadIdx.x + j * 160;
        float v = 0.f;
        if (n < N_COLS) {
            const float* w = (n < 100) ? wq : (n < 200) ? wk : wv;
            int c = (n < 100) ? n : (n < 200) ? n - 100 : n - 200;
            v = w[wb + c];
        }
        __nv_bfloat16 h = __float2bfloat16(v);
        g_Bh[kb + n] = h;
        g_Bl[kb + n] = __float2bfloat16(v - __bfloat162float(h));
    }
}

// ---------------------------------------------------------------------------
// Projection GEMM: mma.sync bf16, error-compensated (Ah*Bh + Ah*Bl + Al*Bh)
// grid = (2 N-tiles, 26 M-tiles, 8 k-splits) = 416 CTAs, 256 thr, occ 3 -> 1 wave
// ---------------------------------------------------------------------------
__global__ __launch_bounds__(NTHREADS, 3)
void proj_mma(const float* __restrict__ x, const float* __restrict__ fwd,
              const float* __restrict__ bwd)
{
    extern __shared__ char smem[];
    const uint32_t sb = smem_u32(smem);
    const int tid  = threadIdx.x;
    const int lane = tid & 31;
    const int wid  = tid >> 5;                 // 0..7
    const int m_w  = (wid >> 2) * 32;          // 0,32
    const int n_w  = (wid & 3) * 40;           // 0,40,80,120

    const int n0 = blockIdx.x * BN;
    const int m0 = blockIdx.y * BM;
    const int ks = blockIdx.z;
    const int k0 = ks * K_PER;

    // ---- A gmem pointer: thread owns 1 row, 8 consecutive k ----
    const int arow = tid >> 2;                 // 0..63
    const int akq  = (tid & 3) * 8;            // 0,8,16,24
    const float* abase;
    {
        int r = m0 + arow;
        if (r >= M_ROWS) r = M_ROWS - 1;       // clamp (stores guarded)
        int b = r / TPAD, t = r - b * TPAD;
        abase = (t == 0)        ? fwd + (size_t)b * DIM
              : (t == TPAD - 1) ? bwd + (size_t)b * DIM
              :                   x + ((size_t)b * SEQ + (t - 1)) * DIM;
        abase += k0 + akq;
    }

    // ---- per-lane ldmatrix address components ----
    const int a_lrow = (lane & 7) + ((lane >> 3) & 1) * 8;
    const int a_lk   = (lane >> 4) * 8;
    const int b_lk   = (lane & 7) + ((lane >> 3) & 1) * 8;

    float acc[2][5][4];
#pragma unroll
    for (int mi = 0; mi < 2; mi++)
#pragma unroll
        for (int ni = 0; ni < 5; ni++)
#pragma unroll
            for (int q = 0; q < 4; q++) acc[mi][ni][q] = 0.f;

    // ---- B staging via cp.async: 1280 x 16B per chunk = 5 per thread ----
    auto stage_B = [&](int c) {
        const uint32_t stg = sb + (c & 1) * STAGE_BYTES;
        const size_t krow = (size_t)(k0 + c * KC);
#pragma unroll
        for (int j = 0; j < 5; j++) {
            int idx = tid + j * NTHREADS;              // 0..1279
            int mat = (idx >= 640);
            int rem = mat ? idx - 640 : idx;
            int r = rem / 20, u = rem - r * 20;
            const __nv_bfloat16* g = mat ? g_Bl : g_Bh;
            const __nv_bfloat16* src = g + (krow + r) * NPAD + n0 + u * 8;
            uint32_t dst = stg + (mat ? ST_BL : ST_BH)
                         + (uint32_t)r * PITCH_BK + (uint32_t)u * 16;
            CP16(dst, src);
        }
        CP_COMMIT();
    };

    float4 pa0, pa1;   // A chunk pending conversion+STS
    auto load_A = [&](int c) {
        pa0 = *(const float4*)(abase + c * KC);
        pa1 = *(const float4*)(abase + c * KC + 4);
    };
    auto store_A = [&](int c) {
        char* stp = smem + (c & 1) * STAGE_BYTES;
        __nv_bfloat162 h0 = __floats2bfloat162_rn(pa0.x, pa0.y);
        __nv_bfloat162 h1 = __floats2bfloat162_rn(pa0.z, pa0.w);
        __nv_bfloat162 h2 = __floats2bfloat162_rn(pa1.x, pa1.y);
        __nv_bfloat162 h3 = __floats2bfloat162_rn(pa1.z, pa1.w);
        float2 f0 = __bfloat1622float2(h0), f1 = __bfloat1622float2(h1);
        float2 f2 = __bfloat1622float2(h2), f3 = __bfloat1622float2(h3);
        __nv_bfloat162 l0 = __floats2bfloat162_rn(pa0.x - f0.x, pa0.y - f0.y);
        __nv_bfloat162 l1 = __floats2bfloat162_rn(pa0.z - f1.x, pa0.w - f1.y);
        __nv_bfloat162 l2 = __floats2bfloat162_rn(pa1.x - f2.x, pa1.y - f2.y);
        __nv_bfloat162 l3 = __floats2bfloat162_rn(pa1.z - f3.x, pa1.w - f3.y);
        uint32_t off = (uint32_t)arow * PITCH_A + (uint32_t)akq * 2;
        *(uint4*)(stp + ST_AH + off) = make_uint4(
            *(uint32_t*)&h0, *(uint32_t*)&h1, *(uint32_t*)&h2, *(uint32_t*)&h3);
        *(uint4*)(stp + ST_AL + off) = make_uint4(
            *(uint32_t*)&l0, *(uint32_t*)&l1, *(uint32_t*)&l2, *(uint32_t*)&l3);
    };

    // ---- prologue: both stages filled ----
    load_A(0);
    stage_B(0);            // group 0
    store_A(0);
    load_A(1);
    stage_B(1);            // group 1
    store_A(1);
    load_A(2);
    CP_WAIT1();            // B(0) complete
    __syncthreads();       // stage 0 visible

    for (int c = 0; c < NCHUNK; c++) {
        const uint32_t stg = sb + (c & 1) * STAGE_BYTES;

        // ---- compute chunk c ----
#pragma unroll
        for (int kk = 0; kk < 2; kk++) {
            uint32_t Ah[2][4], Al[2][4];
#pragma unroll
            for (int mi = 0; mi < 2; mi++) {
                uint32_t aoff = (uint32_t)(m_w + mi * 16 + a_lrow) * PITCH_A
                              + (uint32_t)(kk * 16 + a_lk) * 2;
                ldmx4(Ah[mi], stg + ST_AH + aoff);
                ldmx4(Al[mi], stg + ST_AL + aoff);
            }
            const uint32_t brow = (uint32_t)(kk * 16 + b_lk) * PITCH_BK;
#pragma unroll
            for (int ni = 0; ni < 5; ni++) {
                uint32_t Bh[2], Bl[2];
                uint32_t boff = brow + (uint32_t)(n_w + ni * 8) * 2;
                ldmx2t(Bh, stg + ST_BH + boff);
                ldmx2t(Bl, stg + ST_BL + boff);
#pragma unroll
                for (int mi = 0; mi < 2; mi++) {
                    mma_bf16(acc[mi][ni], Ah[mi], Bh);
                    mma_bf16(acc[mi][ni], Ah[mi], Bl);
                    mma_bf16(acc[mi][ni], Al[mi], Bh);
                }
            }
        }
        __syncthreads();                   // all readers of stage c&1 done

        if (c + 2 < NCHUNK) {
            store_A(c + 2);                // STS into freed stage (c&1)
            stage_B(c + 2);                // cp.async into freed stage
            if (c + 3 < NCHUNK) load_A(c + 3);
            CP_WAIT1();                    // B(c+1) complete
        } else {
            CP_WAIT0();
        }
        __syncthreads();                   // stage (c+1)&1 fully visible
    }

    // ---- writeback to split-K scratch ----
    float* dst = g_Y[ks];
#pragma unroll
    for (int mi = 0; mi < 2; mi++) {
        int row0 = m0 + m_w + mi * 16 + (lane >> 2);
#pragma unroll
        for (int ni = 0; ni < 5; ni++) {
            int col = n0 + n_w + ni * 8 + (lane & 3) * 2;
            if (col < N_COLS) {
                if (row0 < M_ROWS)
                    *(float2*)(dst + (size_t)row0 * N_COLS + col) =
                        make_float2(acc[mi][ni][0], acc[mi][ni][1]);
                if (row0 + 8 < M_ROWS)
                    *(float2*)(dst + (size_t)(row0 + 8) * N_COLS + col) =
                        make_float2(acc[mi][ni][2], acc[mi][ni][3]);
            }
        }
    }
}

// ---------------------------------------------------------------------------
// split-K reduce + 3-tap local attention (w=1 row only)
// ---------------------------------------------------------------------------
__global__ __launch_bounds__(128)
void attn_epilogue(float* __restrict__ out)
{
    __shared__ float sq[PDIM];
    __shared__ float sk[3][PDIM];
    __shared__ float sv[3][PDIM];
    __shared__ float ssc[3];

    const int bs = blockIdx.x;
    const int b  = bs / SEQ;
    const int s  = bs - b * SEQ;
    const int tid = threadIdx.x;
    const size_t rowbase = (size_t)(b * TPAD + s) * N_COLS;

    for (int idx = tid; idx < 7 * PDIM; idx += 128) {
        size_t off;
        if (idx < PDIM) {
            off = rowbase + N_COLS + idx;                                  // q(s+1)
        } else if (idx < 4 * PDIM) {
            int u = (idx - PDIM) / PDIM, c = (idx - PDIM) - u * PDIM;
            off = rowbase + (size_t)u * N_COLS + PDIM + c;                 // k
        } else {
            int u = (idx - 4 * PDIM) / PDIM, c = (idx - 4 * PDIM) - u * PDIM;
            off = rowbase + (size_t)u * N_COLS + 2 * PDIM + c;             // v
        }
        float v = 0.f;
#pragma unroll
        for (int ksi = 0; ksi < KSPLITS; ksi++) v += g_Y[ksi][off];
        if (idx < PDIM)          sq[idx] = v;
        else if (idx < 4 * PDIM) sk[(idx - PDIM) / PDIM][(idx - PDIM) % PDIM] = v;
        else                     sv[(idx - 4 * PDIM) / PDIM][(idx - 4 * PDIM) % PDIM] = v;
    }
    __syncthreads();

    const int warp = tid >> 5, lane = tid & 31;
    if (warp < 3) {
        float p = 0.f;
        for (int c = lane; c < PDIM; c += 32) p += sq[c] * sk[warp][c];
#pragma unroll
        for (int o = 16; o; o >>= 1) p += __shfl_xor_sync(0xffffffffu, p, o);
        if (lane == 0) ssc[warp] = p;
    }
    __syncthreads();

    const float s0 = ssc[0], s1 = ssc[1], s2 = ssc[2];
    const float mx = fmaxf(s0, fmaxf(s1, s2));
    float e0 = expf(s0 - mx), e1 = expf(s1 - mx), e2 = expf(s2 - mx);
    const float inv = 1.f / (e0 + e1 + e2);
    e0 *= inv; e1 *= inv; e2 *= inv;

    if (tid < PDIM)
        out[(size_t)bs * PDIM + tid] = e0 * sv[0][tid] + e1 * sv[1][tid] + e2 * sv[2][tid];
}

// ---------------------------------------------------------------------------
extern "C" void kernel_launch(void* const* d_in, const int* in_sizes, int n_in,
                              void* d_out, int out_size)
{
    (void)in_sizes; (void)n_in; (void)out_size;
    const float* x   = (const float*)d_in[0];
    const float* wq  = (const float*)d_in[1];
    const float* wk  = (const float*)d_in[2];
    const float* wv  = (const float*)d_in[3];
    const float* fwd = (const float*)d_in[4];
    const float* bwd = (const float*)d_in[5];
    float* out = (float*)d_out;

    static bool attr_set = false;
    if (!attr_set) {
        cudaFuncSetAttribute(proj_mma, cudaFuncAttributeMaxDynamicSharedMemorySize,
                             SMEM_TOTAL);
        attr_set = true;
    }

    conv_w<<<DIM, 160>>>(wq, wk, wv);
    proj_mma<<<dim3(NPAD / BN, (M_ROWS + BM - 1) / BM, KSPLITS), NTHREADS, SMEM_TOTAL>>>(
        x, fwd, bwd);
    attn_epilogue<<<BATCH * SEQ, 128>>>(out);
}

// round 13
// speedup vs baseline: 1.2017x; 1.2017x over previous
#include <cuda_runtime.h>
#include <cuda_bf16.h>
#include <cstdint>

// ---------------- problem constants ----------------
#define BATCH 16
#define SEQ   100
#define DIM   8192
#define PDIM  100
#define TPAD  102
#define M_ROWS 1632
#define N_COLS 300
#define NPAD   320
#define KSPLITS 8
#define K_PER  (DIM / KSPLITS)    // 1024
#define KC     32                 // k per chunk
#define NCHUNK (K_PER / KC)       // 32

// GEMM tiling
#define BM 64
#define BN 160
#define NTHREADS 256

// ---------------- global scratch ----------------
__device__ float g_Y[KSPLITS][M_ROWS * N_COLS];            // 15.7 MB
// weights: tf32-rounded fp32, TRANSPOSED [n][k] (n: 0-99 wq, 100-199 wk,
// 200-299 wv, 300-319 zero)
__device__ float g_Bt[(size_t)NPAD * DIM];                 // 10.5 MB

// ---------------- smem layout ----------------
// pitch = 32 tf32 (128B) + 16B pad = 144B (odd 16B multiple -> conflict-free)
#define PITCH 144
#define ST_A 0
#define ST_B (BM * PITCH)                        // 9216
#define STAGE_BYTES ((BM + BN) * PITCH)          // 32256
#define SMEM_TOTAL (2 * STAGE_BYTES)             // 64512

// ---------------- helpers ----------------
__device__ __forceinline__ uint32_t smem_u32(const void* p) {
    uint32_t a;
    asm("{ .reg .u64 t; cvta.to.shared.u64 t, %1; cvt.u32.u64 %0, t; }" : "=r"(a) : "l"(p));
    return a;
}
__device__ __forceinline__ uint32_t f2tf32(float f) {
    uint32_t r;
    asm("cvt.rna.tf32.f32 %0, %1;" : "=r"(r) : "f"(f));
    return r;
}
__device__ __forceinline__ void ldmx4(uint32_t (&r)[4], uint32_t addr) {
    asm volatile("ldmatrix.sync.aligned.m8n8.x4.shared.b16 {%0,%1,%2,%3}, [%4];"
                 : "=r"(r[0]), "=r"(r[1]), "=r"(r[2]), "=r"(r[3]) : "r"(addr));
}
__device__ __forceinline__ void ldmx2(uint32_t (&r)[2], uint32_t addr) {
    asm volatile("ldmatrix.sync.aligned.m8n8.x2.shared.b16 {%0,%1}, [%2];"
                 : "=r"(r[0]), "=r"(r[1]) : "r"(addr));
}
__device__ __forceinline__ void mma_tf32(float (&d)[4], const uint32_t (&a)[4],
                                         const uint32_t (&b)[2]) {
    asm volatile("mma.sync.aligned.m16n8k8.row.col.f32.tf32.tf32.f32 "
                 "{%0,%1,%2,%3},{%4,%5,%6,%7},{%8,%9},{%0,%1,%2,%3};"
                 : "+f"(d[0]), "+f"(d[1]), "+f"(d[2]), "+f"(d[3])
                 : "r"(a[0]), "r"(a[1]), "r"(a[2]), "r"(a[3]), "r"(b[0]), "r"(b[1]));
}
#define CP16(dst, src) \
    asm volatile("cp.async.cg.shared.global [%0], [%1], 16;" :: "r"(dst), "l"(src))
#define CP_COMMIT() asm volatile("cp.async.commit_group;" ::: "memory")
#define CP_WAIT1()  asm volatile("cp.async.wait_group 1;" ::: "memory")
#define CP_WAIT0()  asm volatile("cp.async.wait_group 0;" ::: "memory")

// ---------------------------------------------------------------------------
// Pre-pass: tf32-round + transpose weights into g_Bt[n][k].
// grid = (DIM/32, NPAD/32), 256 threads, 32x32 smem tiles.
// ---------------------------------------------------------------------------
__global__ __launch_bounds__(256)
void conv_w(const float* __restrict__ wq, const float* __restrict__ wk,
            const float* __restrict__ wv)
{
    __shared__ float t[32][33];
    const int kb = blockIdx.x * 32;
    const int nb = blockIdx.y * 32;
    const int tx = threadIdx.x & 31;
    const int ty = threadIdx.x >> 5;          // 0..7

    const int n = nb + tx;
    const float* w = (n < 100) ? wq : (n < 200) ? wk : wv;
    const int c = (n < 100) ? n : (n < 200) ? n - 100 : n - 200;

#pragma unroll
    for (int i = 0; i < 4; i++) {
        int kl = ty + i * 8;
        float v = (n < N_COLS) ? w[(size_t)(kb + kl) * PDIM + c] : 0.f;
        t[tx][kl] = __uint_as_float(f2tf32(v));
    }
    __syncthreads();

#pragma unroll
    for (int i = 0; i < 4; i++) {
        int nl = ty + i * 8;
        g_Bt[(size_t)(nb + nl) * DIM + kb + tx] = t[nl][tx];
    }
}

// ---------------------------------------------------------------------------
// Projection GEMM: mma.sync m16n8k8 tf32, single product.
// grid = (2 N-tiles, 26 M-tiles, 8 k-splits) = 416 CTAs, 256 threads.
// B via cp.async 2-stage from g_Bt[n][k]; A via reg conversion (fp32 -> tf32).
// ---------------------------------------------------------------------------
__global__ __launch_bounds__(NTHREADS, 2)
void proj_mma(const float* __restrict__ x, const float* __restrict__ fwd,
              const float* __restrict__ bwd)
{
    extern __shared__ char smem[];
    const uint32_t sb = smem_u32(smem);
    const int tid  = threadIdx.x;
    const int lane = tid & 31;
    const int wid  = tid >> 5;                 // 0..7
    const int m_w  = (wid >> 2) * 32;          // 0,32
    const int n_w  = (wid & 3) * 40;           // 0,40,80,120

    const int n0 = blockIdx.x * BN;
    const int m0 = blockIdx.y * BM;
    const int ks = blockIdx.z;
    const int k0 = ks * K_PER;

    // ---- A gmem pointer: thread owns 1 row, 8 consecutive k ----
    const int arow = tid >> 2;                 // 0..63
    const int akq  = (tid & 3) * 8;            // 0,8,16,24
    const float* abase;
    {
        int r = m0 + arow;
        if (r >= M_ROWS) r = M_ROWS - 1;       // clamp (stores guarded)
        int b = r / TPAD, t = r - b * TPAD;
        abase = (t == 0)        ? fwd + (size_t)b * DIM
              : (t == TPAD - 1) ? bwd + (size_t)b * DIM
              :                   x + ((size_t)b * SEQ + (t - 1)) * DIM;
        abase += k0 + akq;
    }

    // ---- per-lane ldmatrix address components ----
    // A (x4): lane L supplies row addr for matrix L>>3:
    //   row = m_w + mi*16 + (L&7) + ((L>>3)&1)*8 ; byte col = s*32 + ((L>>4))*16
    const int a_r = (lane & 7) + ((lane >> 3) & 1) * 8;
    const int a_c16 = (lane >> 4) * 16;              // 0 or 16 bytes
    // B (x2): lanes 0..15: row n = n_w + ni*8 + (L&7); byte col = s*32 + ((L>>3)&1)*16
    const int b_r = lane & 7;
    const int b_c16 = ((lane >> 3) & 1) * 16;

    float acc[2][5][4];
#pragma unroll
    for (int mi = 0; mi < 2; mi++)
#pragma unroll
        for (int ni = 0; ni < 5; ni++)
#pragma unroll
            for (int q = 0; q < 4; q++) acc[mi][ni][q] = 0.f;

    // ---- B staging via cp.async: 1280 x 16B per chunk = 5 per thread ----
    auto stage_B = [&](int c) {
        const uint32_t stg = sb + (c & 1) * STAGE_BYTES;
        const int kc = k0 + c * KC;
#pragma unroll
        for (int j = 0; j < 5; j++) {
            int idx = tid + j * NTHREADS;      // 0..1279
            int r = idx >> 3, u = idx & 7;     // row n (0..159), 16B unit (0..7)
            const float* src = g_Bt + (size_t)(n0 + r) * DIM + kc + u * 4;
            uint32_t dst = stg + ST_B + (uint32_t)r * PITCH + (uint32_t)u * 16;
            CP16(dst, src);
        }
        CP_COMMIT();
    };

    float4 pa0, pa1;   // A chunk pending conversion+STS
    auto load_A = [&](int c) {
        pa0 = *(const float4*)(abase + c * KC);
        pa1 = *(const float4*)(abase + c * KC + 4);
    };
    auto store_A = [&](int c) {
        char* stp = smem + (c & 1) * STAGE_BYTES;
        uint32_t off = (uint32_t)arow * PITCH + (uint32_t)akq * 4;
        *(uint4*)(stp + ST_A + off) = make_uint4(
            f2tf32(pa0.x), f2tf32(pa0.y), f2tf32(pa0.z), f2tf32(pa0.w));
        *(uint4*)(stp + ST_A + off + 16) = make_uint4(
            f2tf32(pa1.x), f2tf32(pa1.y), f2tf32(pa1.z), f2tf32(pa1.w));
    };

    // ---- prologue: both stages filled ----
    load_A(0);
    stage_B(0);
    store_A(0);
    load_A(1);
    stage_B(1);
    store_A(1);
    load_A(2);
    CP_WAIT1();            // B(0) complete
    __syncthreads();       // stage 0 visible

    for (int c = 0; c < NCHUNK; c++) {
        const uint32_t stg = sb + (c & 1) * STAGE_BYTES;

        // ---- compute chunk c: 4 k8 steps ----
#pragma unroll
        for (int s = 0; s < 4; s++) {
            uint32_t A0[2][4];
#pragma unroll
            for (int mi = 0; mi < 2; mi++) {
                uint32_t aoff = (uint32_t)(m_w + mi * 16 + a_r) * PITCH
                              + (uint32_t)(s * 32 + a_c16);
                ldmx4(A0[mi], stg + ST_A + aoff);
            }
#pragma unroll
            for (int ni = 0; ni < 5; ni++) {
                uint32_t B0[2];
                uint32_t boff = (uint32_t)(n_w + ni * 8 + b_r) * PITCH
                              + (uint32_t)(s * 32 + b_c16);
                ldmx2(B0, stg + ST_B + boff);
                mma_tf32(acc[0][ni], A0[0], B0);
                mma_tf32(acc[1][ni], A0[1], B0);
            }
        }
        __syncthreads();                   // all readers of stage c&1 done

        if (c + 2 < NCHUNK) {
            store_A(c + 2);                // STS into freed stage (c&1)
            stage_B(c + 2);                // cp.async into freed stage
            if (c + 3 < NCHUNK) load_A(c + 3);
            CP_WAIT1();                    // B(c+1) complete
        } else {
            CP_WAIT0();
        }
        __syncthreads();                   // stage (c+1)&1 fully visible
    }

    // ---- writeback to split-K scratch ----
    float* dst = g_Y[ks];
#pragma unroll
    for (int mi = 0; mi < 2; mi++) {
        int row0 = m0 + m_w + mi * 16 + (lane >> 2);
#pragma unroll
        for (int ni = 0; ni < 5; ni++) {
            int col = n0 + n_w + ni * 8 + (lane & 3) * 2;
            if (col < N_COLS) {
                if (row0 < M_ROWS)
                    *(float2*)(dst + (size_t)row0 * N_COLS + col) =
                        make_float2(acc[mi][ni][0], acc[mi][ni][1]);
                if (row0 + 8 < M_ROWS)
                    *(float2*)(dst + (size_t)(row0 + 8) * N_COLS + col) =
                        make_float2(acc[mi][ni][2], acc[mi][ni][3]);
            }
        }
    }
}

// ---------------------------------------------------------------------------
// split-K reduce + 3-tap local attention (w=1 row only)
// ---------------------------------------------------------------------------
__global__ __launch_bounds__(128)
void attn_epilogue(float* __restrict__ out)
{
    __shared__ float sq[PDIM];
    __shared__ float sk[3][PDIM];
    __shared__ float sv[3][PDIM];
    __shared__ float ssc[3];

    const int bs = blockIdx.x;
    const int b  = bs / SEQ;
    const int s  = bs - b * SEQ;
    const int tid = threadIdx.x;
    const size_t rowbase = (size_t)(b * TPAD + s) * N_COLS;

    for (int idx = tid; idx < 7 * PDIM; idx += 128) {
        size_t off;
        if (idx < PDIM) {
            off = rowbase + N_COLS + idx;                                  // q(s+1)
        } else if (idx < 4 * PDIM) {
            int u = (idx - PDIM) / PDIM, c = (idx - PDIM) - u * PDIM;
            off = rowbase + (size_t)u * N_COLS + PDIM + c;                 // k
        } else {
            int u = (idx - 4 * PDIM) / PDIM, c = (idx - 4 * PDIM) - u * PDIM;
            off = rowbase + (size_t)u * N_COLS + 2 * PDIM + c;             // v
        }
        float v = 0.f;
#pragma unroll
        for (int ksi = 0; ksi < KSPLITS; ksi++) v += g_Y[ksi][off];
        if (idx < PDIM)          sq[idx] = v;
        else if (idx < 4 * PDIM) sk[(idx - PDIM) / PDIM][(idx - PDIM) % PDIM] = v;
        else                     sv[(idx - 4 * PDIM) / PDIM][(idx - 4 * PDIM) % PDIM] = v;
    }
    __syncthreads();

    const int warp = tid >> 5, lane = tid & 31;
    if (warp < 3) {
        float p = 0.f;
        for (int c = lane; c < PDIM; c += 32) p += sq[c] * sk[warp][c];
#pragma unroll
        for (int o = 16; o; o >>= 1) p += __shfl_xor_sync(0xffffffffu, p, o);
        if (lane == 0) ssc[warp] = p;
    }
    __syncthreads();

    const float s0 = ssc[0], s1 = ssc[1], s2 = ssc[2];
    const float mx = fmaxf(s0, fmaxf(s1, s2));
    float e0 = expf(s0 - mx), e1 = expf(s1 - mx), e2 = expf(s2 - mx);
    const float inv = 1.f / (e0 + e1 + e2);
    e0 *= inv; e1 *= inv; e2 *= inv;

    if (tid < PDIM)
        out[(size_t)bs * PDIM + tid] = e0 * sv[0][tid] + e1 * sv[1][tid] + e2 * sv[2][tid];
}

// ---------------------------------------------------------------------------
extern "C" void kernel_launch(void* const* d_in, const int* in_sizes, int n_in,
                              void* d_out, int out_size)
{
    (void)in_sizes; (void)n_in; (void)out_size;
    const float* x   = (const float*)d_in[0];
    const float* wq  = (const float*)d_in[1];
    const float* wk  = (const float*)d_in[2];
    const float* wv  = (const float*)d_in[3];
    const float* fwd = (const float*)d_in[4];
    const float* bwd = (const float*)d_in[5];
    float* out = (float*)d_out;

    static bool attr_set = false;
    if (!attr_set) {
        cudaFuncSetAttribute(proj_mma, cudaFuncAttributeMaxDynamicSharedMemorySize,
                             SMEM_TOTAL);
        attr_set = true;
    }

    conv_w<<<dim3(DIM / 32, NPAD / 32), 256>>>(wq, wk, wv);
    proj_mma<<<dim3(NPAD / BN, (M_ROWS + BM - 1) / BM, KSPLITS), NTHREADS, SMEM_TOTAL>>>(
        x, fwd, bwd);
    attn_epilogue<<<BATCH * SEQ, 128>>>(out);
}

// round 17
// speedup vs baseline: 1.3935x; 1.1596x over previous
#include <cuda_runtime.h>
#include <cuda_bf16.h>
#include <cstdint>

// ---------------- problem constants ----------------
#define BATCH 16
#define SEQ   100
#define DIM   8192
#define PDIM  100
#define TPAD  102
#define M_ROWS 1632
#define N_COLS 300
#define NPAD   320
#define KSPLITS 8
#define K_PER  (DIM / KSPLITS)    // 1024
#define KC     32                 // k per chunk
#define NCHUNK (K_PER / KC)       // 32

// GEMM tiling: 17 exact M-tiles of 96, 2 N-tiles of 160
#define BM 96
#define BN 160
#define NTHREADS 256

// ---------------- global scratch ----------------
__device__ float g_Y[KSPLITS][M_ROWS * N_COLS];            // 15.7 MB
// weights: tf32-rounded fp32, TRANSPOSED [n][k]
__device__ float g_Bt[(size_t)NPAD * DIM];                 // 10.5 MB

// ---------------- smem layout ----------------
// pitch = 32 tf32 (128B) + 16B pad = 144B (odd 16B multiple -> conflict-free)
#define PITCH 144
#define ST_A 0
#define ST_B (BM * PITCH)                        // 13824
#define STAGE_BYTES ((BM + BN) * PITCH)          // 36864
#define SMEM_TOTAL (2 * STAGE_BYTES)             // 73728 -> 2 CTAs/SM

// ---------------- helpers ----------------
__device__ __forceinline__ uint32_t smem_u32(const void* p) {
    uint32_t a;
    asm("{ .reg .u64 t; cvta.to.shared.u64 t, %1; cvt.u32.u64 %0, t; }" : "=r"(a) : "l"(p));
    return a;
}
__device__ __forceinline__ uint32_t f2tf32(float f) {
    uint32_t r;
    asm("cvt.rna.tf32.f32 %0, %1;" : "=r"(r) : "f"(f));
    return r;
}
__device__ __forceinline__ void ldmx4(uint32_t (&r)[4], uint32_t addr) {
    asm volatile("ldmatrix.sync.aligned.m8n8.x4.shared.b16 {%0,%1,%2,%3}, [%4];"
                 : "=r"(r[0]), "=r"(r[1]), "=r"(r[2]), "=r"(r[3]) : "r"(addr));
}
__device__ __forceinline__ void ldmx2(uint32_t (&r)[2], uint32_t addr) {
    asm volatile("ldmatrix.sync.aligned.m8n8.x2.shared.b16 {%0,%1}, [%2];"
                 : "=r"(r[0]), "=r"(r[1]) : "r"(addr));
}
__device__ __forceinline__ void mma_tf32(float (&d)[4], const uint32_t (&a)[4],
                                         const uint32_t (&b)[2]) {
    asm volatile("mma.sync.aligned.m16n8k8.row.col.f32.tf32.tf32.f32 "
                 "{%0,%1,%2,%3},{%4,%5,%6,%7},{%8,%9},{%0,%1,%2,%3};"
                 : "+f"(d[0]), "+f"(d[1]), "+f"(d[2]), "+f"(d[3])
                 : "r"(a[0]), "r"(a[1]), "r"(a[2]), "r"(a[3]), "r"(b[0]), "r"(b[1]));
}
#define CP16(dst, src) \
    asm volatile("cp.async.cg.shared.global [%0], [%1], 16;" :: "r"(dst), "l"(src))
#define CP_COMMIT() asm volatile("cp.async.commit_group;" ::: "memory")
#define CP_WAIT1()  asm volatile("cp.async.wait_group 1;" ::: "memory")
#define CP_WAIT0()  asm volatile("cp.async.wait_group 0;" ::: "memory")

// ---------------------------------------------------------------------------
// Pre-pass: tf32-round + transpose weights into g_Bt[n][k].
// grid = (DIM/32, NPAD/32), 256 threads, 32x32 smem tiles.
// ---------------------------------------------------------------------------
__global__ __launch_bounds__(256)
void conv_w(const float* __restrict__ wq, const float* __restrict__ wk,
            const float* __restrict__ wv)
{
    __shared__ float t[32][33];
    const int kb = blockIdx.x * 32;
    const int nb = blockIdx.y * 32;
    const int tx = threadIdx.x & 31;
    const int ty = threadIdx.x >> 5;          // 0..7

    const int n = nb + tx;
    const float* w = (n < 100) ? wq : (n < 200) ? wk : wv;
    const int c = (n < 100) ? n : (n < 200) ? n - 100 : n - 200;

#pragma unroll
    for (int i = 0; i < 4; i++) {
        int kl = ty + i * 8;
        float v = (n < N_COLS) ? w[(size_t)(kb + kl) * PDIM + c] : 0.f;
        t[tx][kl] = __uint_as_float(f2tf32(v));
    }
    __syncthreads();

#pragma unroll
    for (int i = 0; i < 4; i++) {
        int nl = ty + i * 8;
        g_Bt[(size_t)(nb + nl) * DIM + kb + tx] = t[nl][tx];
    }
}

// ---------------------------------------------------------------------------
// Projection GEMM: mma.sync m16n8k8 tf32, single product.
// grid = (2 N-tiles, 17 M-tiles, 8 k-splits) = 272 CTAs, 256 threads, occ 2.
// Warp grid 2x4, warp tile 48x40.
// ---------------------------------------------------------------------------
__global__ __launch_bounds__(NTHREADS, 2)
void proj_mma(const float* __restrict__ x, const float* __restrict__ fwd,
              const float* __restrict__ bwd)
{
    extern __shared__ char smem[];
    const uint32_t sb = smem_u32(smem);
    const int tid  = threadIdx.x;
    const int lane = tid & 31;
    const int wid  = tid >> 5;                 // 0..7
    const int m_w  = (wid >> 2) * 48;          // 0,48
    const int n_w  = (wid & 3) * 40;           // 0,40,80,120

    const int n0 = blockIdx.x * BN;
    const int m0 = blockIdx.y * BM;
    const int ks = blockIdx.z;
    const int k0 = ks * K_PER;

    // ---- A gmem pointers: 768 float4 per chunk = 3 per thread ----
    // v = tid + j*256 -> row = v>>3 (0..95), quarter q = v&7 (16B units)
    const float* aP[3];
#pragma unroll
    for (int j = 0; j < 3; j++) {
        int v = tid + j * NTHREADS;
        int r = m0 + (v >> 3);                 // always < M_ROWS (1632 = 17*96)
        int q = v & 7;
        int b = r / TPAD, t = r - b * TPAD;
        const float* base = (t == 0)        ? fwd + (size_t)b * DIM
                          : (t == TPAD - 1) ? bwd + (size_t)b * DIM
                          :                   x + ((size_t)b * SEQ + (t - 1)) * DIM;
        aP[j] = base + k0 + q * 4;
    }

    // ---- per-lane ldmatrix address components ----
    const int a_r   = (lane & 7) + ((lane >> 3) & 1) * 8;
    const int a_c16 = (lane >> 4) * 16;              // 0 or 16 bytes
    const int b_r   = lane & 7;
    const int b_c16 = ((lane >> 3) & 1) * 16;

    float acc[3][5][4];
#pragma unroll
    for (int mi = 0; mi < 3; mi++)
#pragma unroll
        for (int ni = 0; ni < 5; ni++)
#pragma unroll
            for (int q = 0; q < 4; q++) acc[mi][ni][q] = 0.f;

    // ---- B staging via cp.async: 1280 x 16B per chunk = 5 per thread ----
    auto stage_B = [&](int c) {
        const uint32_t stg = sb + (c & 1) * STAGE_BYTES;
        const int kc = k0 + c * KC;
#pragma unroll
        for (int j = 0; j < 5; j++) {
            int idx = tid + j * NTHREADS;      // 0..1279
            int r = idx >> 3, u = idx & 7;     // row n (0..159), 16B unit (0..7)
            const float* src = g_Bt + (size_t)(n0 + r) * DIM + kc + u * 4;
            uint32_t dst = stg + ST_B + (uint32_t)r * PITCH + (uint32_t)u * 16;
            CP16(dst, src);
        }
        CP_COMMIT();
    };

    float4 pa[3];   // A chunk pending conversion+STS (12 regs)
    auto load_A = [&](int c) {
#pragma unroll
        for (int j = 0; j < 3; j++) pa[j] = *(const float4*)(aP[j] + c * KC);
    };
    auto store_A = [&](int c) {
        char* stp = smem + (c & 1) * STAGE_BYTES;
#pragma unroll
        for (int j = 0; j < 3; j++) {
            int v = tid + j * NTHREADS;
            uint32_t off = (uint32_t)(v >> 3) * PITCH + (uint32_t)(v & 7) * 16;
            *(uint4*)(stp + ST_A + off) = make_uint4(
                f2tf32(pa[j].x), f2tf32(pa[j].y), f2tf32(pa[j].z), f2tf32(pa[j].w));
        }
    };

    // ---- prologue: both stages filled ----
    load_A(0);
    stage_B(0);
    store_A(0);
    load_A(1);
    stage_B(1);
    store_A(1);
    load_A(2);
    CP_WAIT1();            // B(0) complete
    __syncthreads();       // stage 0 visible

    for (int c = 0; c < NCHUNK; c++) {
        const uint32_t stg = sb + (c & 1) * STAGE_BYTES;

        // ---- compute chunk c: 4 k8 steps ----
#pragma unroll
        for (int s = 0; s < 4; s++) {
            uint32_t A0[3][4];
#pragma unroll
            for (int mi = 0; mi < 3; mi++) {
                uint32_t aoff = (uint32_t)(m_w + mi * 16 + a_r) * PITCH
                              + (uint32_t)(s * 32 + a_c16);
                ldmx4(A0[mi], stg + ST_A + aoff);
            }
#pragma unroll
            for (int ni = 0; ni < 5; ni++) {
                uint32_t B0[2];
                uint32_t boff = (uint32_t)(n_w + ni * 8 + b_r) * PITCH
                              + (uint32_t)(s * 32 + b_c16);
                ldmx2(B0, stg + ST_B + boff);
#pragma unroll
                for (int mi = 0; mi < 3; mi++)
                    mma_tf32(acc[mi][ni], A0[mi], B0);
            }
        }
        __syncthreads();                   // all readers of stage c&1 done

        if (c + 2 < NCHUNK) {
            store_A(c + 2);                // STS into freed stage (c&1)
            stage_B(c + 2);                // cp.async into freed stage
            if (c + 3 < NCHUNK) load_A(c + 3);
            CP_WAIT1();                    // B(c+1) complete
        } else {
            CP_WAIT0();
        }
        __syncthreads();                   // stage (c+1)&1 fully visible
    }

    // ---- writeback to split-K scratch ----
    float* dst = g_Y[ks];
#pragma unroll
    for (int mi = 0; mi < 3; mi++) {
        int row0 = m0 + m_w + mi * 16 + (lane >> 2);    // always < M_ROWS
#pragma unroll
        for (int ni = 0; ni < 5; ni++) {
            int col = n0 + n_w + ni * 8 + (lane & 3) * 2;
            if (col < N_COLS) {
                *(float2*)(dst + (size_t)row0 * N_COLS + col) =
                    make_float2(acc[mi][ni][0], acc[mi][ni][1]);
                *(float2*)(dst + (size_t)(row0 + 8) * N_COLS + col) =
                    make_float2(acc[mi][ni][2], acc[mi][ni][3]);
            }
        }
    }
}

// ---------------------------------------------------------------------------
// split-K reduce + 3-tap local attention (w=1 row only)
// ---------------------------------------------------------------------------
__global__ __launch_bounds__(128)
void attn_epilogue(float* __restrict__ out)
{
    __shared__ float sq[PDIM];
    __shared__ float sk[3][PDIM];
    __shared__ float sv[3][PDIM];
    __shared__ float ssc[3];

    const int bs = blockIdx.x;
    const int b  = bs / SEQ;
    const int s  = bs - b * SEQ;
    const int tid = threadIdx.x;
    const size_t rowbase = (size_t)(b * TPAD + s) * N_COLS;

    for (int idx = tid; idx < 7 * PDIM; idx += 128) {
        size_t off;
        if (idx < PDIM) {
            off = rowbase + N_COLS + idx;                                  // q(s+1)
        } else if (idx < 4 * PDIM) {
            int u = (idx - PDIM) / PDIM, c = (idx - PDIM) - u * PDIM;
            off = rowbase + (size_t)u * N_COLS + PDIM + c;                 // k
        } else {
            int u = (idx - 4 * PDIM) / PDIM, c = (idx - 4 * PDIM) - u * PDIM;
            off = rowbase + (size_t)u * N_COLS + 2 * PDIM + c;             // v
        }
        float v = 0.f;
#pragma unroll
        for (int ksi = 0; ksi < KSPLITS; ksi++) v += g_Y[ksi][off];
        if (idx < PDIM)          sq[idx] = v;
        else if (idx < 4 * PDIM) sk[(idx - PDIM) / PDIM][(idx - PDIM) % PDIM] = v;
        else                     sv[(idx - 4 * PDIM) / PDIM][(idx - 4 * PDIM) % PDIM] = v;
    }
    __syncthreads();

    const int warp = tid >> 5, lane = tid & 31;
    if (warp < 3) {
        float p = 0.f;
        for (int c = lane; c < PDIM; c += 32) p += sq[c] * sk[warp][c];
#pragma unroll
        for (int o = 16; o; o >>= 1) p += __shfl_xor_sync(0xffffffffu, p, o);
        if (lane == 0) ssc[warp] = p;
    }
    __syncthreads();

    const float s0 = ssc[0], s1 = ssc[1], s2 = ssc[2];
    const float mx = fmaxf(s0, fmaxf(s1, s2));
    float e0 = expf(s0 - mx), e1 = expf(s1 - mx), e2 = expf(s2 - mx);
    const float inv = 1.f / (e0 + e1 + e2);
    e0 *= inv; e1 *= inv; e2 *= inv;

    if (tid < PDIM)
        out[(size_t)bs * PDIM + tid] = e0 * sv[0][tid] + e1 * sv[1][tid] + e2 * sv[2][tid];
}

// ---------------------------------------------------------------------------
extern "C" void kernel_launch(void* const* d_in, const int* in_sizes, int n_in,
                              void* d_out, int out_size)
{
    (void)in_sizes; (void)n_in; (void)out_size;
    const float* x   = (const float*)d_in[0];
    const float* wq  = (const float*)d_in[1];
    const float* wk  = (const float*)d_in[2];
    const float* wv  = (const float*)d_in[3];
    const float* fwd = (const float*)d_in[4];
    const float* bwd = (const float*)d_in[5];
    float* out = (float*)d_out;

    static bool attr_set = false;
    if (!attr_set) {
        cudaFuncSetAttribute(proj_mma, cudaFuncAttributeMaxDynamicSharedMemorySize,
                             SMEM_TOTAL);
        attr_set = true;
    }

    conv_w<<<dim3(DIM / 32, NPAD / 32), 256>>>(wq, wk, wv);
    proj_mma<<<dim3(2, M_ROWS / BM, KSPLITS), NTHREADS, SMEM_TOTAL>>>(x, fwd, bwd);
    attn_epilogue<<<BATCH * SEQ, 128>>>(out);
}